// round 6
// baseline (speedup 1.0000x reference)
#include <cuda_runtime.h>
#include <cstdint>

#define B_ 256
#define T_ 1024
#define D_ 64
#define H_ 100
#define G_ 400   // 4*H
#define NBLK 128
#define L2E 1.44269504088896f

// Precomputed input-gate contributions, PERMUTED row order:
// xg[b][t][p] holds gate-row ((p&3)*H + (p>>2)).  ~419 MB.
__device__ float g_xg[(size_t)B_ * T_ * G_];

// ---------------------------------------------------------------------------
// Packed f32x2 helpers
// ---------------------------------------------------------------------------
__device__ __forceinline__ unsigned long long ffma2(unsigned long long a,
                                                    unsigned long long b,
                                                    unsigned long long c) {
    unsigned long long d;
    asm("fma.rn.f32x2 %0, %1, %2, %3;" : "=l"(d) : "l"(a), "l"(b), "l"(c));
    return d;
}
__device__ __forceinline__ unsigned long long add2(unsigned long long a,
                                                   unsigned long long b) {
    unsigned long long d;
    asm("add.rn.f32x2 %0, %1, %2;" : "=l"(d) : "l"(a), "l"(b));
    return d;
}
__device__ __forceinline__ unsigned long long pack2(float x, float y) {
    return ((unsigned long long)__float_as_uint(y) << 32) |
           (unsigned long long)__float_as_uint(x);
}
__device__ __forceinline__ float lo2(unsigned long long v) {
    return __uint_as_float((unsigned)v);
}
__device__ __forceinline__ float hi2(unsigned long long v) {
    return __uint_as_float((unsigned)(v >> 32));
}
__device__ __forceinline__ float ex2a(float x) {
    float r; asm("ex2.approx.ftz.f32 %0, %1;" : "=f"(r) : "f"(x)); return r;
}
__device__ __forceinline__ float rcpa(float x) {
    float r; asm("rcp.approx.ftz.f32 %0, %1;" : "=f"(r) : "f"(x)); return r;
}
// sigmoid(x) = 1 - 1/(e^x+1)  (lm=log2e, s=1);  tanh(x) = 1 - 2/(e^2x+1)
__device__ __forceinline__ float uact(float x, float lm, float s) {
    return 1.0f - s * rcpa(ex2a(lm * x) + 1.0f);
}

// ---------------------------------------------------------------------------
// Kernel 1: xg[b,t,p] = x[b,t,:] . W_ih[row,:] + (b_ih+b_hh)[row],
//           row = (p&3)*H + (p>>2)  (quad-permuted for the lstm kernel).
// Results staged in shared in 8-t chunks, then stored as CONTIGUOUS float4s
// (each 8-t chunk of [b][t][p] is 12.8KB contiguous) — kills the 32x sector
// amplification of the per-thread strided STG.32.
// ---------------------------------------------------------------------------
__global__ __launch_bounds__(512, 1)
void xg_kernel(const float* __restrict__ x,
               const float* __restrict__ W_ih,
               const float* __restrict__ b_ih,
               const float* __restrict__ b_hh) {
    __shared__ ulonglong2 xs[64][16];   // 64 t x 64 k fp32 tile (16 KB)
    __shared__ float stage[8][G_];      // 8-t output staging (12.8 KB)

    const int b   = blockIdx.y;
    const int t0  = blockIdx.x * 64;
    const int tid = threadIdx.x;

    {   // coalesced float4 tile load
        const float4* src = (const float4*)(x + ((size_t)b * T_ + t0) * D_);
        float4* dst = (float4*)xs;
        for (int i = tid; i < 64 * 16; i += 512) dst[i] = src[i];
    }

    unsigned long long w2[32];
    float bias = 0.0f;
    if (tid < G_) {
        const int row = (tid & 3) * H_ + (tid >> 2);
        const float4* wrow = (const float4*)(W_ih + (size_t)row * D_);
#pragma unroll
        for (int i = 0; i < 16; i++) {
            float4 v = wrow[i];
            w2[2 * i]     = pack2(v.x, v.y);
            w2[2 * i + 1] = pack2(v.z, v.w);
        }
        bias = b_ih[row] + b_hh[row];
    }
    __syncthreads();

    float4* outc = (float4*)(g_xg + ((size_t)b * T_ + t0) * G_);

    for (int chunk = 0; chunk < 8; chunk++) {
        if (tid < G_) {
#pragma unroll
            for (int tc = 0; tc < 8; tc++) {
                const int t = chunk * 8 + tc;
                unsigned long long a0 = 0ull, a1 = 0ull;
#pragma unroll
                for (int i = 0; i < 16; i++) {
                    ulonglong2 xv = xs[t][i];      // broadcast LDS.128
                    a0 = ffma2(w2[2 * i],     xv.x, a0);
                    a1 = ffma2(w2[2 * i + 1], xv.y, a1);
                }
                unsigned long long s2 = add2(a0, a1);
                stage[tc][tid] = lo2(s2) + hi2(s2) + bias;
            }
        }
        __syncthreads();
        {   // contiguous coalesced store of 8*400 floats = 800 float4
            const float4* sf = (const float4*)stage;
            float4* dst = outc + (size_t)chunk * (8 * G_ / 4);
            for (int i = tid; i < 8 * G_ / 4; i += 512) dst[i] = sf[i];
        }
        __syncthreads();
    }
}

// ---------------------------------------------------------------------------
// Kernel 2: recurrence, split-k, ONE barrier per step. (R5 — best measured.)
// 128 blocks x 2 batch rows, 800 threads. Thread: r = tid>>1 (permuted row,
// gate=r&3, j=r>>2), s = tid&1 (k-half AND final batch owner).
// ---------------------------------------------------------------------------
__global__ __launch_bounds__(800, 1)
void lstm_kernel(const float* __restrict__ h0,
                 const float* __restrict__ c0,
                 const float* __restrict__ W_hh,
                 const float* __restrict__ W_fc,
                 const float* __restrict__ b_fc,
                 float* __restrict__ out) {
    __shared__ float4 hs4[2][50];      // [buf][k-pair i] = {h0_2i,h0_2i+1,h1_2i,h1_2i+1}
    __shared__ float wfc_s[H_];

    const int tid    = threadIdx.x;
    const int batch0 = blockIdx.x * 2;
    const int r      = tid >> 1;       // permuted gate-row
    const int s      = tid & 1;        // k-half + batch owner
    const int gate   = r & 3;
    const int j      = r >> 2;

    // --- init h buffer 0, wfc ---
    if (tid < H_) {
        int i = tid >> 1, comp = tid & 1;
        ((float*)&hs4[0][i])[comp]     = h0[(size_t)(batch0)     * H_ + tid];
        ((float*)&hs4[0][i])[2 + comp] = h0[(size_t)(batch0 + 1) * H_ + tid];
        wfc_s[tid] = W_fc[tid];
    }

    // --- weights: k-pairs [s*25, s*25+25) of W_hh row (gate*H + j) ---
    unsigned long long w2[25];
    {
        const float2* wrow =
            (const float2*)(W_hh + (size_t)(gate * H_ + j) * H_) + s * 25;
#pragma unroll
        for (int i = 0; i < 25; i++) {
            float2 v = wrow[i];
            w2[i] = pack2(v.x, v.y);
        }
    }
    float lm = (gate == 2) ? 2.0f * L2E : L2E;
    float sc = (gate == 2) ? 2.0f : 1.0f;

    // c owned by gate-0 threads: (unit j, batch s)
    float cr = (gate == 0) ? c0[(size_t)(batch0 + s) * H_ + j] : 0.0f;

    // xg stream for my batch (batch0+s), permuted row r
    const float* xp = g_xg + (size_t)(batch0 + s) * T_ * G_ + r;
    float xgc = xp[0];

    __syncthreads();

    int cur = 0;
    for (int t = 0; t < T_; t++) {
        float xgn = (t + 1 < T_) ? xp[(size_t)(t + 1) * G_] : 0.0f;  // prefetch

        // matvec over my k-half, both batches from one load + one weight reg
        const float4* hbase = hs4[cur] + s * 25;
        unsigned long long a0 = 0ull, b0 = 0ull;
#pragma unroll
        for (int i = 0; i < 25; i++) {
            float4 hv = hbase[i];                  // LDS.128
            a0 = ffma2(w2[i], pack2(hv.x, hv.y), a0);
            b0 = ffma2(w2[i], pack2(hv.z, hv.w), b0);
        }
        float p0 = lo2(a0) + hi2(a0);              // batch0 partial (my half)
        float p1 = lo2(b0) + hi2(b0);              // batch1 partial

        // combine k-halves with partner lane (tid^1)
        float q0 = __shfl_xor_sync(0xffffffffu, p0, 1);
        float q1 = __shfl_xor_sync(0xffffffffu, p1, 1);
        float full = (s ? (p1 + q1) : (p0 + q0)) + xgc;

        float gv = uact(full, lm, sc);             // my gate, my batch

        // gather {f,g,o} to the gate-0 lane (even deltas keep batch parity)
        float fv = __shfl_down_sync(0xffffffffu, gv, 2);
        float gg = __shfl_down_sync(0xffffffffu, gv, 4);
        float ov = __shfl_down_sync(0xffffffffu, gv, 6);

        if (gate == 0) {                           // owns c for (j, batch s)
            cr = fv * cr + gv * gg;
            float hv = ov * uact(cr, 2.0f * L2E, 2.0f);
            ((float*)&hs4[cur ^ 1][j >> 1])[(j & 1) + 2 * s] = hv;
        }
        xgc = xgn;
        __syncthreads();
        cur ^= 1;
    }

    // FC head: out[b] = h_T . W_fc + b_fc   (h_T is in hs4[cur])
    if (tid < 2) {
        float acc = b_fc[0];
#pragma unroll 4
        for (int jj = 0; jj < H_; jj++) {
            float hv = ((const float*)&hs4[cur][jj >> 1])[(jj & 1) + 2 * tid];
            acc += hv * wfc_s[jj];
        }
        out[batch0 + tid] = acc;
    }
}

// ---------------------------------------------------------------------------
extern "C" void kernel_launch(void* const* d_in, const int* in_sizes, int n_in,
                              void* d_out, int out_size) {
    const float* x    = (const float*)d_in[0];
    const float* h0   = (const float*)d_in[1];
    const float* c0   = (const float*)d_in[2];
    const float* W_ih = (const float*)d_in[3];
    const float* W_hh = (const float*)d_in[4];
    const float* b_ih = (const float*)d_in[5];
    const float* b_hh = (const float*)d_in[6];
    const float* W_fc = (const float*)d_in[7];
    const float* b_fc = (const float*)d_in[8];
    float* out = (float*)d_out;

    dim3 grid1(T_ / 64, B_);
    xg_kernel<<<grid1, 512>>>(x, W_ih, b_ih, b_hh);

    lstm_kernel<<<NBLK, 800>>>(h0, c0, W_hh, W_fc, b_fc, out);
}